// round 13
// baseline (speedup 1.0000x reference)
#include <cuda_runtime.h>
#include <cstdint>

#define N_NODES 100000
#define N_EDGES 1000000
#define IN_CH   32
#define EDGE_CH 16
#define OUT_CH  32
#define D_MID   56

typedef unsigned long long u64;

static __device__ int g_is64;
static __device__ __align__(16) float g_XR[N_NODES * D_MID];  // x@W1[0:32]+b1
static __device__ __align__(16) float g_XC[N_NODES * D_MID];  // x@W1[32:64]
static __device__ __align__(16) float4 g_H[(size_t)N_EDGES * 14];  // H row-major [e][56]

// ---- packed f32x2 helpers ---------------------------------------------------
__device__ __forceinline__ u64 pk2(float a, float b) {
    u64 r; asm("mov.b64 %0, {%1,%2};" : "=l"(r) : "f"(a), "f"(b)); return r;
}
__device__ __forceinline__ void upk2(float& a, float& b, u64 v) {
    asm("mov.b64 {%0,%1}, %2;" : "=f"(a), "=f"(b) : "l"(v));
}
#define FMA2(d, a, b, c) asm("fma.rn.f32x2 %0, %1, %2, %3;" : "=l"(d) : "l"(a), "l"(b), "l"(c))
#define ADD2(d, a, b)    asm("add.rn.f32x2 %0, %1, %2;"     : "=l"(d) : "l"(a), "l"(b))

__device__ __forceinline__ void atomicMaxF(float* addr, float val) {
    if (val >= 0.0f) atomicMax(reinterpret_cast<int*>(addr), __float_as_int(val));
    else             atomicMin(reinterpret_cast<unsigned int*>(addr), __float_as_uint(val));
}

// ---------------------------------------------------------------------------
// K0: init output to -inf + (block 0) detect int64 vs int32 edge_index
// ---------------------------------------------------------------------------
__global__ void k_pre(const unsigned int* __restrict__ w, unsigned int* __restrict__ out) {
    if (blockIdx.x == 0) {
        __shared__ int bad;
        if (threadIdx.x == 0) bad = 0;
        __syncthreads();
        for (int i = threadIdx.x; i < 4096; i += blockDim.x)
            if (w[2 * i + 1] != 0u) bad = 1;   // benign race
        __syncthreads();
        if (threadIdx.x == 0) g_is64 = !bad;
    }
    int stride = gridDim.x * blockDim.x;
    for (int i = blockIdx.x * blockDim.x + threadIdx.x; i < N_NODES * OUT_CH; i += stride)
        out[i] = 0xFF800000u;  // -inf
}

// ---------------------------------------------------------------------------
// K1: per-node precompute (scalar fp32, j-blocked — proven round 6)
// ---------------------------------------------------------------------------
__global__ void __launch_bounds__(128, 8) k_node(const float* __restrict__ x,
                                                 const float* __restrict__ W1,
                                                 const float* __restrict__ b1) {
    __shared__ __align__(16) float sW[2 * IN_CH * D_MID];
    __shared__ __align__(16) float sb[D_MID];
    for (int i = threadIdx.x; i < 2 * IN_CH * D_MID; i += blockDim.x) sW[i] = W1[i];
    for (int i = threadIdx.x; i < D_MID; i += blockDim.x) sb[i] = b1[i];
    __syncthreads();

    int n = blockIdx.x * blockDim.x + threadIdx.x;
    if (n >= N_NODES) return;

    float xr[IN_CH];
    const float4* xp = reinterpret_cast<const float4*>(x + n * IN_CH);
#pragma unroll
    for (int c = 0; c < 8; c++) {
        float4 v = xp[c];
        xr[4 * c + 0] = v.x; xr[4 * c + 1] = v.y; xr[4 * c + 2] = v.z; xr[4 * c + 3] = v.w;
    }

#pragma unroll
    for (int which = 0; which < 2; which++) {
        float* dstbase = (which == 0 ? g_XR : g_XC) + (size_t)n * D_MID;
        const float* Wbase = sW + which * IN_CH * D_MID;
#pragma unroll
        for (int jb = 0; jb < D_MID / 8; jb++) {
            u64 hb0, hb1, hb2, hb3;
            if (which == 0) {
                const ulonglong2* bp = reinterpret_cast<const ulonglong2*>(&sb[8 * jb]);
                ulonglong2 b01 = bp[0], b23 = bp[1];
                hb0 = b01.x; hb1 = b01.y; hb2 = b23.x; hb3 = b23.y;
            } else {
                hb0 = hb1 = hb2 = hb3 = 0ull;
            }
#pragma unroll
            for (int k = 0; k < IN_CH; k++) {
                u64 aa = pk2(xr[k], xr[k]);
                const ulonglong2* w = reinterpret_cast<const ulonglong2*>(Wbase + k * D_MID + 8 * jb);
                ulonglong2 w0 = w[0], w1 = w[1];
                FMA2(hb0, aa, w0.x, hb0);
                FMA2(hb1, aa, w0.y, hb1);
                FMA2(hb2, aa, w1.x, hb2);
                FMA2(hb3, aa, w1.y, hb3);
            }
            ulonglong2* dst = reinterpret_cast<ulonglong2*>(dstbase + 8 * jb);
            ulonglong2 s0; s0.x = hb0; s0.y = hb1;
            ulonglong2 s1; s1.x = hb2; s1.y = hb3;
            dst[0] = s0; dst[1] = s1;
        }
    }
}

// ---------------------------------------------------------------------------
// K2a: layer 1 -> H.  Half-warp = edge, lane t<14 owns channels 4t..4t+3.
// We (16x56) held in registers; XR/XC gathers are coalesced row reads.
// ---------------------------------------------------------------------------
__global__ void __launch_bounds__(128, 5) k_e1(const int* __restrict__ idx32,
                                               const float* __restrict__ ea,
                                               const float* __restrict__ W1) {
    const int lane = threadIdx.x & 31;
    const int warp = threadIdx.x >> 5;
    const int half = lane >> 4;
    const int t    = lane & 15;
    const bool act = t < 14;
    const int off  = act ? 4 * t : 0;

    // per-lane weight slice: We[k][4t..4t+3], k = 0..15  (64 regs)
    u64 we0[EDGE_CH], we1[EDGE_CH];
    {
        const float* We = W1 + 2 * IN_CH * D_MID;
#pragma unroll
        for (int k = 0; k < EDGE_CH; k++) {
            float4 v = __ldg(reinterpret_cast<const float4*>(We + k * D_MID + off));
            we0[k] = pk2(v.x, v.y);
            we1[k] = pk2(v.z, v.w);
        }
    }

    const int gw = blockIdx.x * 4 + warp;
    const int nw = gridDim.x * 4;
    const int is64 = g_is64;

    for (int ee = gw * 2; ee < N_EDGES; ee += nw * 2) {
        int e = ee + half;
        int rol, col;
        if (is64) { rol = idx32[2 * e]; col = idx32[2 * (N_EDGES + e)]; }
        else      { rol = idx32[e];     col = idx32[N_EDGES + e]; }

        // coalesced row-slice gathers (14 lanes x 16B = one 224B row)
        float4 xr = __ldg(reinterpret_cast<const float4*>(g_XR + (size_t)rol * D_MID + off));
        float4 xc = __ldg(reinterpret_cast<const float4*>(g_XC + (size_t)col * D_MID + off));

        // edge_attr broadcast (all lanes of the half-warp, same address)
        const float4* pe = reinterpret_cast<const float4*>(ea + (size_t)e * EDGE_CH);
        float4 a0 = __ldg(pe), a1 = __ldg(pe + 1), a2 = __ldg(pe + 2), a3 = __ldg(pe + 3);
        float av[EDGE_CH] = {a0.x, a0.y, a0.z, a0.w, a1.x, a1.y, a1.z, a1.w,
                             a2.x, a2.y, a2.z, a2.w, a3.x, a3.y, a3.z, a3.w};

        u64 acc0 = pk2(xr.x + xc.x, xr.y + xc.y);
        u64 acc1 = pk2(xr.z + xc.z, xr.w + xc.w);
#pragma unroll
        for (int k = 0; k < EDGE_CH; k++) {
            u64 aa = pk2(av[k], av[k]);
            FMA2(acc0, aa, we0[k], acc0);
            FMA2(acc1, aa, we1[k], acc1);
        }

        float f0, f1, f2, f3;
        upk2(f0, f1, acc0);
        upk2(f2, f3, acc1);
        f0 = fmaxf(f0, 0.01f * f0);
        f1 = fmaxf(f1, 0.01f * f1);
        f2 = fmaxf(f2, 0.01f * f2);
        f3 = fmaxf(f3, 0.01f * f3);
        if (act)
            g_H[(size_t)e * 14 + t] = make_float4(f0, f1, f2, f3);  // coalesced 224B row
    }
}

// ---------------------------------------------------------------------------
// K2b: layer 2 + scatter-max.  Half-warp = edge, lane owns channels 2t,2t+1.
// W2 (56x32) held entirely in registers (56 u64/lane); zero weight LDS in loop.
// ---------------------------------------------------------------------------
__global__ void __launch_bounds__(128, 3) k_e2(const int* __restrict__ idx32,
                                               const float* __restrict__ W2,
                                               const float* __restrict__ b2,
                                               float* __restrict__ out) {
    const int lane = threadIdx.x & 31;
    const int warp = threadIdx.x >> 5;
    const int half = lane >> 4;
    const int t    = lane & 15;

    // per-lane weight column pair: W2[k][2t..2t+1], k = 0..55  (112 regs)
    u64 w[D_MID];
#pragma unroll
    for (int k = 0; k < D_MID; k++) {
        float2 v = __ldg(reinterpret_cast<const float2*>(W2 + k * OUT_CH + 2 * t));
        w[k] = pk2(v.x, v.y);
    }
    u64 bias;
    {
        float2 v = __ldg(reinterpret_cast<const float2*>(b2 + 2 * t));
        bias = pk2(v.x, v.y);
    }

    const int gw = blockIdx.x * 4 + warp;
    const int nw = gridDim.x * 4;
    const int is64 = g_is64;

    for (int ee = gw * 2; ee < N_EDGES; ee += nw * 2) {
        int e = ee + half;
        int col = is64 ? idx32[2 * (N_EDGES + e)] : idx32[N_EDGES + e];

        u64 acc0 = bias;
        u64 acc1 = pk2(0.0f, 0.0f);
        const float4* hp = g_H + (size_t)e * 14;
#pragma unroll
        for (int q = 0; q < 14; q++) {
            float4 hv = __ldg(hp + q);   // broadcast within half-warp
            FMA2(acc0, pk2(hv.x, hv.x), w[4 * q + 0], acc0);
            FMA2(acc1, pk2(hv.y, hv.y), w[4 * q + 1], acc1);
            FMA2(acc0, pk2(hv.z, hv.z), w[4 * q + 2], acc0);
            FMA2(acc1, pk2(hv.w, hv.w), w[4 * q + 3], acc1);
        }
        ADD2(acc0, acc0, acc1);

        float v0, v1;
        upk2(v0, v1, acc0);
        v0 = fmaxf(v0, 0.01f * v0);
        v1 = fmaxf(v1, 0.01f * v1);

        float* p = out + (size_t)col * OUT_CH + 2 * t;
        float2 cur = *reinterpret_cast<const float2*>(p);  // monotone max: stale OK
        if (v0 > cur.x) atomicMaxF(p, v0);
        if (v1 > cur.y) atomicMaxF(p + 1, v1);
    }
}

// ---------------------------------------------------------------------------
// K3: finalize — -inf -> 0, elementwise max with x (float4)
// ---------------------------------------------------------------------------
__global__ void k_final(const float4* __restrict__ x, float4* __restrict__ out) {
    int i = blockIdx.x * blockDim.x + threadIdx.x;
    if (i >= N_NODES * OUT_CH / 4) return;
    float4 a = out[i];
    float4 b = x[i];
    if (__float_as_uint(a.x) == 0xFF800000u) a.x = 0.0f;
    if (__float_as_uint(a.y) == 0xFF800000u) a.y = 0.0f;
    if (__float_as_uint(a.z) == 0xFF800000u) a.z = 0.0f;
    if (__float_as_uint(a.w) == 0xFF800000u) a.w = 0.0f;
    a.x = fmaxf(a.x, b.x); a.y = fmaxf(a.y, b.y);
    a.z = fmaxf(a.z, b.z); a.w = fmaxf(a.w, b.w);
    out[i] = a;
}

// ---------------------------------------------------------------------------
extern "C" void kernel_launch(void* const* d_in, const int* in_sizes, int n_in,
                              void* d_out, int out_size) {
    const float* x         = (const float*)d_in[0];
    const int*   idx32     = (const int*)d_in[1];
    const float* edge_attr = (const float*)d_in[2];
    const float* W1        = (const float*)d_in[3];
    const float* b1        = (const float*)d_in[4];
    const float* W2        = (const float*)d_in[5];
    const float* b2        = (const float*)d_in[6];
    float* out = (float*)d_out;

    k_pre<<<592, 256>>>((const unsigned int*)d_in[1], (unsigned int*)d_out);
    k_node<<<(N_NODES + 127) / 128, 128>>>(x, W1, b1);
    k_e1<<<740, 128>>>(idx32, edge_attr, W1);    // 5 CTAs/SM persistent
    k_e2<<<444, 128>>>(idx32, W2, b2, out);      // 3 CTAs/SM persistent
    k_final<<<(N_NODES * OUT_CH / 4 + 255) / 256, 256>>>((const float4*)x, (float4*)out);
}

// round 14
// speedup vs baseline: 1.3627x; 1.3627x over previous
#include <cuda_runtime.h>
#include <cstdint>

#define N_NODES 100000
#define N_EDGES 1000000
#define IN_CH   32
#define EDGE_CH 16
#define OUT_CH  32
#define D_MID   56
#define ROW_PAD 60

typedef unsigned long long u64;

static __device__ int g_is64;
static __device__ __align__(16) float g_XR[N_NODES * D_MID];  // x@W1[0:32]+b1
static __device__ __align__(16) float g_XC[N_NODES * D_MID];  // x@W1[32:64]
static __device__ __align__(16) float4 g_H[14 * N_EDGES];     // H[q][e]

// ---- packed f32x2 helpers ---------------------------------------------------
__device__ __forceinline__ u64 pk2(float a, float b) {
    u64 r; asm("mov.b64 %0, {%1,%2};" : "=l"(r) : "f"(a), "f"(b)); return r;
}
__device__ __forceinline__ void upk2(float& a, float& b, u64 v) {
    asm("mov.b64 {%0,%1}, %2;" : "=f"(a), "=f"(b) : "l"(v));
}
#define FMA2(d, a, b, c) asm("fma.rn.f32x2 %0, %1, %2, %3;" : "=l"(d) : "l"(a), "l"(b), "l"(c))
#define MUL2(d, a, b)    asm("mul.rn.f32x2 %0, %1, %2;"     : "=l"(d) : "l"(a), "l"(b))
#define ADD2(d, a, b)    asm("add.rn.f32x2 %0, %1, %2;"     : "=l"(d) : "l"(a), "l"(b))

__device__ __forceinline__ void atomicMaxF(float* addr, float val) {
    if (val >= 0.0f) atomicMax(reinterpret_cast<int*>(addr), __float_as_int(val));
    else             atomicMin(reinterpret_cast<unsigned int*>(addr), __float_as_uint(val));
}

// ---------------------------------------------------------------------------
// K0: one-shot init to -inf (uint4) + detect int64 (block 0)
// ---------------------------------------------------------------------------
__global__ void k_pre(const unsigned int* __restrict__ w, uint4* __restrict__ out) {
    if (blockIdx.x == 0) {
        __shared__ int bad;
        if (threadIdx.x == 0) bad = 0;
        __syncthreads();
        for (int i = threadIdx.x; i < 4096; i += blockDim.x)
            if (w[2 * i + 1] != 0u) bad = 1;   // benign race
        __syncthreads();
        if (threadIdx.x == 0) g_is64 = !bad;
    }
    int i = blockIdx.x * blockDim.x + threadIdx.x;
    if (i < N_NODES * OUT_CH / 4)
        out[i] = make_uint4(0xFF800000u, 0xFF800000u, 0xFF800000u, 0xFF800000u);
}

// ---------------------------------------------------------------------------
// K1: per-node precompute (scalar fp32, j-blocked — proven round 6)
// ---------------------------------------------------------------------------
__global__ void __launch_bounds__(128, 8) k_node(const float* __restrict__ x,
                                                 const float* __restrict__ W1,
                                                 const float* __restrict__ b1) {
    __shared__ __align__(16) float sW[2 * IN_CH * D_MID];
    __shared__ __align__(16) float sb[D_MID];
    for (int i = threadIdx.x; i < 2 * IN_CH * D_MID; i += blockDim.x) sW[i] = W1[i];
    for (int i = threadIdx.x; i < D_MID; i += blockDim.x) sb[i] = b1[i];
    __syncthreads();

    int n = blockIdx.x * blockDim.x + threadIdx.x;
    if (n >= N_NODES) return;

    float xr[IN_CH];
    const float4* xp = reinterpret_cast<const float4*>(x + n * IN_CH);
#pragma unroll
    for (int c = 0; c < 8; c++) {
        float4 v = xp[c];
        xr[4 * c + 0] = v.x; xr[4 * c + 1] = v.y; xr[4 * c + 2] = v.z; xr[4 * c + 3] = v.w;
    }

#pragma unroll
    for (int which = 0; which < 2; which++) {
        float* dstbase = (which == 0 ? g_XR : g_XC) + (size_t)n * D_MID;
        const float* Wbase = sW + which * IN_CH * D_MID;
#pragma unroll
        for (int jb = 0; jb < D_MID / 8; jb++) {
            u64 hb0, hb1, hb2, hb3;
            if (which == 0) {
                const ulonglong2* bp = reinterpret_cast<const ulonglong2*>(&sb[8 * jb]);
                ulonglong2 b01 = bp[0], b23 = bp[1];
                hb0 = b01.x; hb1 = b01.y; hb2 = b23.x; hb3 = b23.y;
            } else {
                hb0 = hb1 = hb2 = hb3 = 0ull;
            }
#pragma unroll
            for (int k = 0; k < IN_CH; k++) {
                u64 aa = pk2(xr[k], xr[k]);
                const ulonglong2* w = reinterpret_cast<const ulonglong2*>(Wbase + k * D_MID + 8 * jb);
                ulonglong2 w0 = w[0], w1 = w[1];
                FMA2(hb0, aa, w0.x, hb0);
                FMA2(hb1, aa, w0.y, hb1);
                FMA2(hb2, aa, w1.x, hb2);
                FMA2(hb3, aa, w1.y, hb3);
            }
            ulonglong2* dst = reinterpret_cast<ulonglong2*>(dstbase + 8 * jb);
            ulonglong2 s0; s0.x = hb0; s0.y = hb1;
            ulonglong2 s1; s1.x = hb2; s1.y = hb3;
            dst[0] = s0; dst[1] = s1;
        }
    }
}

// ---------------------------------------------------------------------------
// K2a: layer 1 -> H.  Warp-cooperative staging; ea@We split in halves so BOTH
// gather stages have FMA cover.
// ---------------------------------------------------------------------------
__device__ __forceinline__ void stage_rows(const float* __restrict__ table,
                                           int row, float* __restrict__ sb,
                                           int half, int sub) {
#pragma unroll
    for (int r2 = 0; r2 < 32; r2 += 2) {
        int src0 = __shfl_sync(0xffffffffu, row, r2);
        int src1 = __shfl_sync(0xffffffffu, row, r2 + 1);
        int src  = half ? src1 : src0;
        int r    = r2 + half;
        if (sub < 14) {
            float4 v = __ldg(reinterpret_cast<const float4*>(table + (size_t)src * D_MID) + sub);
            *reinterpret_cast<float4*>(sb + r * ROW_PAD + sub * 4) = v;
        }
    }
}

__global__ void __launch_bounds__(128) k_e1(const int* __restrict__ idx32,
                                            const float* __restrict__ ea,
                                            const float* __restrict__ W1) {
    __shared__ __align__(16) float sWe[EDGE_CH * D_MID];
    __shared__ __align__(16) float sbuf[4][32 * ROW_PAD];

    const float* We = W1 + 2 * IN_CH * D_MID;
    for (int i = threadIdx.x; i < EDGE_CH * D_MID; i += blockDim.x) sWe[i] = We[i];
    __syncthreads();

    const int warp = threadIdx.x >> 5;
    const int lane = threadIdx.x & 31;
    const int half = lane >> 4;
    const int sub  = lane & 15;
    float* sb = sbuf[warp];

    int e = blockIdx.x * 128 + warp * 32 + lane;
    bool valid = e < N_EDGES;
    int ec = valid ? e : N_EDGES - 1;

    int rol, col;
    if (g_is64) {
        rol = idx32[2 * ec];
        col = idx32[2 * (N_EDGES + ec)];
    } else {
        rol = idx32[ec];
        col = idx32[N_EDGES + ec];
    }

    // edge_attr into registers early
    float av[EDGE_CH];
    {
        const float4* pe = reinterpret_cast<const float4*>(ea + (size_t)ec * EDGE_CH);
        float4 a0 = pe[0], a1 = pe[1], a2 = pe[2], a3 = pe[3];
        av[0] = a0.x;  av[1] = a0.y;  av[2] = a0.z;  av[3] = a0.w;
        av[4] = a1.x;  av[5] = a1.y;  av[6] = a1.z;  av[7] = a1.w;
        av[8] = a2.x;  av[9] = a2.y;  av[10] = a2.z; av[11] = a2.w;
        av[12] = a3.x; av[13] = a3.y; av[14] = a3.z; av[15] = a3.w;
    }

    // ---- stage XR (in flight behind first half of ea@We) ----
    stage_rows(g_XR, rol, sb, half, sub);

    u64 h[D_MID / 2];
#pragma unroll
    for (int k = 0; k < 8; k++) {   // first half of ea@We
        u64 aa = pk2(av[k], av[k]);
        const ulonglong2* w = reinterpret_cast<const ulonglong2*>(&sWe[k * D_MID]);
#pragma unroll
        for (int j = 0; j < D_MID / 4; j++) {
            ulonglong2 ww = w[j];
            if (k == 0) {
                MUL2(h[2 * j],     aa, ww.x);
                MUL2(h[2 * j + 1], aa, ww.y);
            } else {
                FMA2(h[2 * j],     aa, ww.x, h[2 * j]);
                FMA2(h[2 * j + 1], aa, ww.y, h[2 * j + 1]);
            }
        }
    }

    // consume XR
    __syncwarp();
    {
        const ulonglong2* pr = reinterpret_cast<const ulonglong2*>(sb + lane * ROW_PAD);
#pragma unroll
        for (int j = 0; j < D_MID / 4; j++) {
            ulonglong2 a = pr[j];
            ADD2(h[2 * j],     h[2 * j],     a.x);
            ADD2(h[2 * j + 1], h[2 * j + 1], a.y);
        }
    }
    __syncwarp();

    // ---- stage XC (in flight behind second half of ea@We) ----
    stage_rows(g_XC, col, sb, half, sub);

#pragma unroll
    for (int k = 8; k < EDGE_CH; k++) {   // second half of ea@We
        u64 aa = pk2(av[k], av[k]);
        const ulonglong2* w = reinterpret_cast<const ulonglong2*>(&sWe[k * D_MID]);
#pragma unroll
        for (int j = 0; j < D_MID / 4; j++) {
            ulonglong2 ww = w[j];
            FMA2(h[2 * j],     aa, ww.x, h[2 * j]);
            FMA2(h[2 * j + 1], aa, ww.y, h[2 * j + 1]);
        }
    }

    // consume XC
    __syncwarp();
    {
        const ulonglong2* pc = reinterpret_cast<const ulonglong2*>(sb + lane * ROW_PAD);
#pragma unroll
        for (int j = 0; j < D_MID / 4; j++) {
            ulonglong2 a = pc[j];
            ADD2(h[2 * j],     h[2 * j],     a.x);
            ADD2(h[2 * j + 1], h[2 * j + 1], a.y);
        }
    }

    // LeakyReLU + coalesced H store
    if (valid) {
#pragma unroll
        for (int q = 0; q < 14; q++) {
            float a0, a1, a2, a3;
            upk2(a0, a1, h[2 * q]);
            upk2(a2, a3, h[2 * q + 1]);
            a0 = fmaxf(a0, 0.01f * a0);
            a1 = fmaxf(a1, 0.01f * a1);
            a2 = fmaxf(a2, 0.01f * a2);
            a3 = fmaxf(a3, 0.01f * a3);
            g_H[(size_t)q * N_EDGES + e] = make_float4(a0, a1, a2, a3);
        }
    }
}

// ---------------------------------------------------------------------------
// K2b: layer 2 + scatter-max.  H loads pipelined with prefetch distance 5.
// ---------------------------------------------------------------------------
__global__ void __launch_bounds__(128) k_e2(const int* __restrict__ idx32,
                                            const float* __restrict__ W2,
                                            const float* __restrict__ b2,
                                            float* __restrict__ out) {
    __shared__ __align__(16) float sW2[D_MID * OUT_CH];
    __shared__ __align__(16) float sb2[OUT_CH];
    for (int i = threadIdx.x; i < D_MID * OUT_CH; i += blockDim.x) sW2[i] = W2[i];
    for (int i = threadIdx.x; i < OUT_CH; i += blockDim.x) sb2[i] = b2[i];
    __syncthreads();

    int e = blockIdx.x * 128 + threadIdx.x;
    if (e >= N_EDGES) return;

    int col = g_is64 ? idx32[2 * (N_EDGES + e)] : idx32[N_EDGES + e];

    u64 o[OUT_CH / 2];
    {
        const ulonglong2* bp = reinterpret_cast<const ulonglong2*>(sb2);
#pragma unroll
        for (int j = 0; j < OUT_CH / 4; j++) {
            ulonglong2 v = bp[j];
            o[2 * j] = v.x; o[2 * j + 1] = v.y;
        }
    }

    // prefetch ring, distance 5 (MLP >= 5 against ~600cyc latency)
    float4 hbuf[5];
#pragma unroll
    for (int q = 0; q < 5; q++) hbuf[q] = __ldg(&g_H[(size_t)q * N_EDGES + e]);

#pragma unroll
    for (int q = 0; q < 14; q++) {
        float4 hv = hbuf[q % 5];
        if (q + 5 < 14) hbuf[q % 5] = __ldg(&g_H[(size_t)(q + 5) * N_EDGES + e]);
        float hs[4] = {hv.x, hv.y, hv.z, hv.w};
#pragma unroll
        for (int u = 0; u < 4; u++) {
            int k = 4 * q + u;
            u64 aa = pk2(hs[u], hs[u]);
            const ulonglong2* w = reinterpret_cast<const ulonglong2*>(&sW2[k * OUT_CH]);
#pragma unroll
            for (int j = 0; j < OUT_CH / 4; j++) {
                ulonglong2 ww = w[j];
                FMA2(o[2 * j],     aa, ww.x, o[2 * j]);
                FMA2(o[2 * j + 1], aa, ww.y, o[2 * j + 1]);
            }
        }
    }

    // LeakyReLU + filtered scatter-max
    float* orow = out + (size_t)col * OUT_CH;
    const float4* oro = reinterpret_cast<const float4*>(orow);
#pragma unroll
    for (int q = 0; q < OUT_CH / 4; q++) {
        float v0, v1, v2, v3;
        upk2(v0, v1, o[2 * q]);
        upk2(v2, v3, o[2 * q + 1]);
        v0 = fmaxf(v0, 0.01f * v0);
        v1 = fmaxf(v1, 0.01f * v1);
        v2 = fmaxf(v2, 0.01f * v2);
        v3 = fmaxf(v3, 0.01f * v3);
        float4 cur = oro[q];                 // monotone max: stale read is safe
        if (v0 > cur.x) atomicMaxF(orow + 4 * q + 0, v0);
        if (v1 > cur.y) atomicMaxF(orow + 4 * q + 1, v1);
        if (v2 > cur.z) atomicMaxF(orow + 4 * q + 2, v2);
        if (v3 > cur.w) atomicMaxF(orow + 4 * q + 3, v3);
    }
}

// ---------------------------------------------------------------------------
// K3: finalize — -inf -> 0, elementwise max with x (float4)
// ---------------------------------------------------------------------------
__global__ void k_final(const float4* __restrict__ x, float4* __restrict__ out) {
    int i = blockIdx.x * blockDim.x + threadIdx.x;
    if (i >= N_NODES * OUT_CH / 4) return;
    float4 a = out[i];
    float4 b = x[i];
    if (__float_as_uint(a.x) == 0xFF800000u) a.x = 0.0f;
    if (__float_as_uint(a.y) == 0xFF800000u) a.y = 0.0f;
    if (__float_as_uint(a.z) == 0xFF800000u) a.z = 0.0f;
    if (__float_as_uint(a.w) == 0xFF800000u) a.w = 0.0f;
    a.x = fmaxf(a.x, b.x); a.y = fmaxf(a.y, b.y);
    a.z = fmaxf(a.z, b.z); a.w = fmaxf(a.w, b.w);
    out[i] = a;
}

// ---------------------------------------------------------------------------
extern "C" void kernel_launch(void* const* d_in, const int* in_sizes, int n_in,
                              void* d_out, int out_size) {
    const float* x         = (const float*)d_in[0];
    const int*   idx32     = (const int*)d_in[1];
    const float* edge_attr = (const float*)d_in[2];
    const float* W1        = (const float*)d_in[3];
    const float* b1        = (const float*)d_in[4];
    const float* W2        = (const float*)d_in[5];
    const float* b2        = (const float*)d_in[6];
    float* out = (float*)d_out;

    const int eg = (N_EDGES + 127) / 128;
    k_pre<<<(N_NODES * OUT_CH / 4 + 255) / 256, 256>>>((const unsigned int*)d_in[1], (uint4*)d_out);
    k_node<<<(N_NODES + 127) / 128, 128>>>(x, W1, b1);
    k_e1<<<eg, 128>>>(idx32, edge_attr, W1);
    k_e2<<<eg, 128>>>(idx32, W2, b2, out);
    k_final<<<(N_NODES * OUT_CH / 4 + 255) / 256, 256>>>((const float4*)x, (float4*)out);
}

// round 15
// speedup vs baseline: 1.4502x; 1.0642x over previous
#include <cuda_runtime.h>
#include <cstdint>

#define N_NODES 100000
#define N_EDGES 1000000
#define IN_CH   32
#define EDGE_CH 16
#define OUT_CH  32
#define D_MID   56
#define ROW_PAD 60

typedef unsigned long long u64;

static __device__ int g_is64;
static __device__ __align__(16) float g_XR[N_NODES * D_MID];  // x@W1[0:32]+b1
static __device__ __align__(16) float g_XC[N_NODES * D_MID];  // x@W1[32:64]

// ---- packed f32x2 helpers ---------------------------------------------------
__device__ __forceinline__ u64 pk2(float a, float b) {
    u64 r; asm("mov.b64 %0, {%1,%2};" : "=l"(r) : "f"(a), "f"(b)); return r;
}
__device__ __forceinline__ void upk2(float& a, float& b, u64 v) {
    asm("mov.b64 {%0,%1}, %2;" : "=f"(a), "=f"(b) : "l"(v));
}
#define FMA2(d, a, b, c) asm("fma.rn.f32x2 %0, %1, %2, %3;" : "=l"(d) : "l"(a), "l"(b), "l"(c))
#define MUL2(d, a, b)    asm("mul.rn.f32x2 %0, %1, %2;"     : "=l"(d) : "l"(a), "l"(b))
#define ADD2(d, a, b)    asm("add.rn.f32x2 %0, %1, %2;"     : "=l"(d) : "l"(a), "l"(b))

__device__ __forceinline__ void atomicMaxF(float* addr, float val) {
    if (val >= 0.0f) atomicMax(reinterpret_cast<int*>(addr), __float_as_int(val));
    else             atomicMin(reinterpret_cast<unsigned int*>(addr), __float_as_uint(val));
}

// ---------------------------------------------------------------------------
// K0: one-shot init to -inf (uint4) + detect int64 (block 0)
// ---------------------------------------------------------------------------
__global__ void k_pre(const unsigned int* __restrict__ w, uint4* __restrict__ out) {
    if (blockIdx.x == 0) {
        __shared__ int bad;
        if (threadIdx.x == 0) bad = 0;
        __syncthreads();
        for (int i = threadIdx.x; i < 4096; i += blockDim.x)
            if (w[2 * i + 1] != 0u) bad = 1;   // benign race
        __syncthreads();
        if (threadIdx.x == 0) g_is64 = !bad;
    }
    int i = blockIdx.x * blockDim.x + threadIdx.x;
    if (i < N_NODES * OUT_CH / 4)
        out[i] = make_uint4(0xFF800000u, 0xFF800000u, 0xFF800000u, 0xFF800000u);
}

// ---------------------------------------------------------------------------
// K1: per-node precompute (scalar fp32, j-blocked — proven round 6)
// ---------------------------------------------------------------------------
__global__ void __launch_bounds__(128, 8) k_node(const float* __restrict__ x,
                                                 const float* __restrict__ W1,
                                                 const float* __restrict__ b1) {
    __shared__ __align__(16) float sW[2 * IN_CH * D_MID];
    __shared__ __align__(16) float sb[D_MID];
    for (int i = threadIdx.x; i < 2 * IN_CH * D_MID; i += blockDim.x) sW[i] = W1[i];
    for (int i = threadIdx.x; i < D_MID; i += blockDim.x) sb[i] = b1[i];
    __syncthreads();

    int n = blockIdx.x * blockDim.x + threadIdx.x;
    if (n >= N_NODES) return;

    float xr[IN_CH];
    const float4* xp = reinterpret_cast<const float4*>(x + n * IN_CH);
#pragma unroll
    for (int c = 0; c < 8; c++) {
        float4 v = xp[c];
        xr[4 * c + 0] = v.x; xr[4 * c + 1] = v.y; xr[4 * c + 2] = v.z; xr[4 * c + 3] = v.w;
    }

#pragma unroll
    for (int which = 0; which < 2; which++) {
        float* dstbase = (which == 0 ? g_XR : g_XC) + (size_t)n * D_MID;
        const float* Wbase = sW + which * IN_CH * D_MID;
#pragma unroll
        for (int jb = 0; jb < D_MID / 8; jb++) {
            u64 hb0, hb1, hb2, hb3;
            if (which == 0) {
                const ulonglong2* bp = reinterpret_cast<const ulonglong2*>(&sb[8 * jb]);
                ulonglong2 b01 = bp[0], b23 = bp[1];
                hb0 = b01.x; hb1 = b01.y; hb2 = b23.x; hb3 = b23.y;
            } else {
                hb0 = hb1 = hb2 = hb3 = 0ull;
            }
#pragma unroll
            for (int k = 0; k < IN_CH; k++) {
                u64 aa = pk2(xr[k], xr[k]);
                const ulonglong2* w = reinterpret_cast<const ulonglong2*>(Wbase + k * D_MID + 8 * jb);
                ulonglong2 w0 = w[0], w1 = w[1];
                FMA2(hb0, aa, w0.x, hb0);
                FMA2(hb1, aa, w0.y, hb1);
                FMA2(hb2, aa, w1.x, hb2);
                FMA2(hb3, aa, w1.y, hb3);
            }
            ulonglong2* dst = reinterpret_cast<ulonglong2*>(dstbase + 8 * jb);
            ulonglong2 s0; s0.x = hb0; s0.y = hb1;
            ulonglong2 s1; s1.x = hb2; s1.y = hb3;
            dst[0] = s0; dst[1] = s1;
        }
    }
}

// ---------------------------------------------------------------------------
// K2: FUSED edge kernel.  Warp = 32 edges.
//   A: layer 1 thread=edge (staged XR/XC + ea@We)      [R11-proven]
//   B: LeakyReLU + transpose h -> Hs[k][e] in warp smem
//   C: layer 2 GEMM-tiled: thread = 4 edges x 8 channels
//   D: transposed epilogue: lane = channel, coalesced filter + atomics
// ---------------------------------------------------------------------------
__device__ __forceinline__ void stage_rows(const float* __restrict__ table,
                                           int row, float* __restrict__ sb,
                                           int half, int sub) {
#pragma unroll
    for (int r2 = 0; r2 < 32; r2 += 2) {
        int src0 = __shfl_sync(0xffffffffu, row, r2);
        int src1 = __shfl_sync(0xffffffffu, row, r2 + 1);
        int src  = half ? src1 : src0;
        int r    = r2 + half;
        if (sub < 14) {
            float4 v = __ldg(reinterpret_cast<const float4*>(table + (size_t)src * D_MID) + sub);
            *reinterpret_cast<float4*>(sb + r * ROW_PAD + sub * 4) = v;
        }
    }
}

__global__ void __launch_bounds__(128, 4) k_edge(const int* __restrict__ idx32,
                                                 const float* __restrict__ ea,
                                                 const float* __restrict__ W1,
                                                 const float* __restrict__ W2,
                                                 const float* __restrict__ b2,
                                                 float* __restrict__ out) {
    __shared__ __align__(16) float sWe[EDGE_CH * D_MID];      // 3584 B
    __shared__ __align__(16) float sW2[D_MID * OUT_CH];       // 7168 B  [k][ch]
    __shared__ __align__(16) float sb2[OUT_CH];
    __shared__ int scol[4][32];
    __shared__ __align__(16) float wbuf[4][32 * ROW_PAD];     // 4 x 7680 B

    const float* We = W1 + 2 * IN_CH * D_MID;
    for (int i = threadIdx.x; i < EDGE_CH * D_MID; i += blockDim.x) sWe[i] = We[i];
    for (int i = threadIdx.x; i < D_MID * OUT_CH; i += blockDim.x) sW2[i] = W2[i];
    for (int i = threadIdx.x; i < OUT_CH; i += blockDim.x) sb2[i] = b2[i];
    __syncthreads();

    const int warp = threadIdx.x >> 5;
    const int lane = threadIdx.x & 31;
    const int half = lane >> 4;
    const int sub  = lane & 15;
    float* sb = wbuf[warp];
    const int ebase = blockIdx.x * 128 + warp * 32;

    int e = ebase + lane;
    bool valid = e < N_EDGES;
    int ec = valid ? e : N_EDGES - 1;

    int rol, col;
    if (g_is64) {
        rol = idx32[2 * ec];
        col = idx32[2 * (N_EDGES + ec)];
    } else {
        rol = idx32[ec];
        col = idx32[N_EDGES + ec];
    }
    scol[warp][lane] = col;

    // ================= Phase A: layer 1 (thread = edge) =================
    stage_rows(g_XR, rol, sb, half, sub);

    u64 h[D_MID / 2];
    {
        const float4* pe = reinterpret_cast<const float4*>(ea + (size_t)ec * EDGE_CH);
        float av[EDGE_CH];
#pragma unroll
        for (int c = 0; c < 4; c++) {
            float4 v = pe[c];
            av[4 * c + 0] = v.x; av[4 * c + 1] = v.y; av[4 * c + 2] = v.z; av[4 * c + 3] = v.w;
        }
#pragma unroll
        for (int k = 0; k < EDGE_CH; k++) {
            u64 aa = pk2(av[k], av[k]);
            const ulonglong2* w = reinterpret_cast<const ulonglong2*>(&sWe[k * D_MID]);
#pragma unroll
            for (int j = 0; j < D_MID / 4; j++) {
                ulonglong2 ww = w[j];
                if (k == 0) {
                    MUL2(h[2 * j],     aa, ww.x);
                    MUL2(h[2 * j + 1], aa, ww.y);
                } else {
                    FMA2(h[2 * j],     aa, ww.x, h[2 * j]);
                    FMA2(h[2 * j + 1], aa, ww.y, h[2 * j + 1]);
                }
            }
        }
    }
    __syncwarp();
    {
        const ulonglong2* pr = reinterpret_cast<const ulonglong2*>(sb + lane * ROW_PAD);
#pragma unroll
        for (int j = 0; j < D_MID / 4; j++) {
            ulonglong2 a = pr[j];
            ADD2(h[2 * j],     h[2 * j],     a.x);
            ADD2(h[2 * j + 1], h[2 * j + 1], a.y);
        }
    }
    __syncwarp();
    stage_rows(g_XC, col, sb, half, sub);
    __syncwarp();
    {
        const ulonglong2* pc = reinterpret_cast<const ulonglong2*>(sb + lane * ROW_PAD);
#pragma unroll
        for (int j = 0; j < D_MID / 4; j++) {
            ulonglong2 a = pc[j];
            ADD2(h[2 * j],     h[2 * j],     a.x);
            ADD2(h[2 * j + 1], h[2 * j + 1], a.y);
        }
    }
    __syncwarp();   // all lanes done reading staging rows before overwrite

    // ============== Phase B: LeakyReLU + transpose -> Hs[k][e] ==============
#pragma unroll
    for (int j = 0; j < D_MID / 2; j++) {
        float a, b; upk2(a, b, h[j]);
        a = fmaxf(a, 0.01f * a);
        b = fmaxf(b, 0.01f * b);
        sb[(2 * j) * 32 + lane]     = a;
        sb[(2 * j + 1) * 32 + lane] = b;
    }
    __syncwarp();

    // ====== Phase C: layer 2 GEMM-tiled (thread = 4 edges x 8 channels) ======
    const int eg = lane >> 2;   // edge group 0..7  -> edges eg*4 .. eg*4+3
    const int cg = lane & 3;    // channel group    -> channels cg*8 .. cg*8+7

    u64 o[16];                  // o[4i+j]: edge eg*4+i, channel pair cg*8+2j
    {
        const ulonglong2* bp = reinterpret_cast<const ulonglong2*>(sb2 + cg * 8);
        ulonglong2 b0 = bp[0], b1 = bp[1];
#pragma unroll
        for (int i = 0; i < 4; i++) {
            o[4 * i + 0] = b0.x; o[4 * i + 1] = b0.y;
            o[4 * i + 2] = b1.x; o[4 * i + 3] = b1.y;
        }
    }
#pragma unroll 8
    for (int k = 0; k < D_MID; k++) {
        float4 hv = *reinterpret_cast<const float4*>(sb + k * 32 + eg * 4);
        const ulonglong2* wp = reinterpret_cast<const ulonglong2*>(&sW2[k * OUT_CH + cg * 8]);
        ulonglong2 wa = wp[0], wb = wp[1];
        float hh[4] = {hv.x, hv.y, hv.z, hv.w};
#pragma unroll
        for (int i = 0; i < 4; i++) {
            u64 aa = pk2(hh[i], hh[i]);
            FMA2(o[4 * i + 0], aa, wa.x, o[4 * i + 0]);
            FMA2(o[4 * i + 1], aa, wa.y, o[4 * i + 1]);
            FMA2(o[4 * i + 2], aa, wb.x, o[4 * i + 2]);
            FMA2(o[4 * i + 3], aa, wb.y, o[4 * i + 3]);
        }
    }
    __syncwarp();   // Hs fully consumed before Os overwrites wbuf

    // ====== Phase D: LeakyReLU, Os[e][ch] transpose, coalesced epilogue ======
#pragma unroll
    for (int i = 0; i < 4; i++) {
        int el = eg * 4 + i;
        float f0, f1, f2, f3, f4, f5, f6, f7;
        upk2(f0, f1, o[4 * i + 0]);
        upk2(f2, f3, o[4 * i + 1]);
        upk2(f4, f5, o[4 * i + 2]);
        upk2(f6, f7, o[4 * i + 3]);
        f0 = fmaxf(f0, 0.01f * f0); f1 = fmaxf(f1, 0.01f * f1);
        f2 = fmaxf(f2, 0.01f * f2); f3 = fmaxf(f3, 0.01f * f3);
        f4 = fmaxf(f4, 0.01f * f4); f5 = fmaxf(f5, 0.01f * f5);
        f6 = fmaxf(f6, 0.01f * f6); f7 = fmaxf(f7, 0.01f * f7);
        *reinterpret_cast<float4*>(sb + el * 36 + cg * 8)     = make_float4(f0, f1, f2, f3);
        *reinterpret_cast<float4*>(sb + el * 36 + cg * 8 + 4) = make_float4(f4, f5, f6, f7);
    }
    __syncwarp();

#pragma unroll 4
    for (int el = 0; el < 32; el++) {
        if (ebase + el >= N_EDGES) break;          // warp-uniform
        int c = scol[warp][el];
        float v = sb[el * 36 + lane];              // lane = channel
        float* p = out + (size_t)c * OUT_CH + lane;
        float cur = *p;                            // coalesced 128B row; stale OK
        if (v > cur) atomicMaxF(p, v);
    }
}

// ---------------------------------------------------------------------------
// K3: finalize — -inf -> 0, elementwise max with x (float4)
// ---------------------------------------------------------------------------
__global__ void k_final(const float4* __restrict__ x, float4* __restrict__ out) {
    int i = blockIdx.x * blockDim.x + threadIdx.x;
    if (i >= N_NODES * OUT_CH / 4) return;
    float4 a = out[i];
    float4 b = x[i];
    if (__float_as_uint(a.x) == 0xFF800000u) a.x = 0.0f;
    if (__float_as_uint(a.y) == 0xFF800000u) a.y = 0.0f;
    if (__float_as_uint(a.z) == 0xFF800000u) a.z = 0.0f;
    if (__float_as_uint(a.w) == 0xFF800000u) a.w = 0.0f;
    a.x = fmaxf(a.x, b.x); a.y = fmaxf(a.y, b.y);
    a.z = fmaxf(a.z, b.z); a.w = fmaxf(a.w, b.w);
    out[i] = a;
}

// ---------------------------------------------------------------------------
extern "C" void kernel_launch(void* const* d_in, const int* in_sizes, int n_in,
                              void* d_out, int out_size) {
    const float* x         = (const float*)d_in[0];
    const int*   idx32     = (const int*)d_in[1];
    const float* edge_attr = (const float*)d_in[2];
    const float* W1        = (const float*)d_in[3];
    const float* b1        = (const float*)d_in[4];
    const float* W2        = (const float*)d_in[5];
    const float* b2        = (const float*)d_in[6];
    float* out = (float*)d_out;

    k_pre<<<(N_NODES * OUT_CH / 4 + 255) / 256, 256>>>((const unsigned int*)d_in[1], (uint4*)d_out);
    k_node<<<(N_NODES + 127) / 128, 128>>>(x, W1, b1);
    k_edge<<<(N_EDGES + 127) / 128, 128>>>(idx32, edge_attr, W1, W2, b2, out);
    k_final<<<(N_NODES * OUT_CH / 4 + 255) / 256, 256>>>((const float4*)x, (float4*)out);
}

// round 16
// speedup vs baseline: 1.5240x; 1.0508x over previous
#include <cuda_runtime.h>
#include <cstdint>

#define N_NODES 100000
#define N_EDGES 1000000
#define IN_CH   32
#define EDGE_CH 16
#define OUT_CH  32
#define D_MID   56
#define EA_PAD  17   // edge_attr smem row stride (conflict-free: 17 coprime 32)

typedef unsigned long long u64;

static __device__ int   g_is64;
static __device__ __align__(16) float g_XR[N_NODES * D_MID];  // x @ W1[0:32]  + b1
static __device__ __align__(16) float g_XC[N_NODES * D_MID];  // x @ W1[32:64]

// ---- packed f32x2 helpers ---------------------------------------------------
__device__ __forceinline__ u64 pk2(float a, float b) {
    u64 r; asm("mov.b64 %0, {%1,%2};" : "=l"(r) : "f"(a), "f"(b)); return r;
}
__device__ __forceinline__ void upk2(float& a, float& b, u64 v) {
    asm("mov.b64 {%0,%1}, %2;" : "=f"(a), "=f"(b) : "l"(v));
}
#define FMA2(d, a, b, c) asm("fma.rn.f32x2 %0, %1, %2, %3;" : "=l"(d) : "l"(a), "l"(b), "l"(c))
#define MUL2(d, a, b)    asm("mul.rn.f32x2 %0, %1, %2;"     : "=l"(d) : "l"(a), "l"(b))
#define ADD2(d, a, b)    asm("add.rn.f32x2 %0, %1, %2;"     : "=l"(d) : "l"(a), "l"(b))

__device__ __forceinline__ void atomicMaxF(float* addr, float val) {
    if (val >= 0.0f) atomicMax(reinterpret_cast<int*>(addr), __float_as_int(val));
    else             atomicMin(reinterpret_cast<unsigned int*>(addr), __float_as_uint(val));
}

// ---------------------------------------------------------------------------
// K0: one-shot init to -inf (uint4) + detect int64 (block 0)
// ---------------------------------------------------------------------------
__global__ void k_pre(const unsigned int* __restrict__ w, uint4* __restrict__ out) {
    if (blockIdx.x == 0) {
        __shared__ int bad;
        if (threadIdx.x == 0) bad = 0;
        __syncthreads();
        for (int i = threadIdx.x; i < 4096; i += blockDim.x)
            if (w[2 * i + 1] != 0u) bad = 1;   // benign race
        __syncthreads();
        if (threadIdx.x == 0) g_is64 = !bad;
    }
    int i = blockIdx.x * blockDim.x + threadIdx.x;
    if (i < N_NODES * OUT_CH / 4)
        out[i] = make_uint4(0xFF800000u, 0xFF800000u, 0xFF800000u, 0xFF800000u);
}

// ---------------------------------------------------------------------------
// K1: per-node precompute, j-blocked (low regs -> high occupancy)  [round 6]
// ---------------------------------------------------------------------------
__global__ void __launch_bounds__(128, 8) k_node(const float* __restrict__ x,
                                                 const float* __restrict__ W1,
                                                 const float* __restrict__ b1) {
    __shared__ __align__(16) float sW[2 * IN_CH * D_MID];  // 14336 B
    __shared__ __align__(16) float sb[D_MID];
    for (int i = threadIdx.x; i < 2 * IN_CH * D_MID; i += blockDim.x) sW[i] = W1[i];
    for (int i = threadIdx.x; i < D_MID; i += blockDim.x) sb[i] = b1[i];
    __syncthreads();

    int n = blockIdx.x * blockDim.x + threadIdx.x;
    if (n >= N_NODES) return;

    float xr[IN_CH];
    const float4* xp = reinterpret_cast<const float4*>(x + n * IN_CH);
#pragma unroll
    for (int c = 0; c < 8; c++) {
        float4 v = xp[c];
        xr[4 * c + 0] = v.x; xr[4 * c + 1] = v.y; xr[4 * c + 2] = v.z; xr[4 * c + 3] = v.w;
    }

#pragma unroll
    for (int which = 0; which < 2; which++) {
        float* dstbase = (which == 0 ? g_XR : g_XC) + (size_t)n * D_MID;
        const float* Wbase = sW + which * IN_CH * D_MID;
#pragma unroll
        for (int jb = 0; jb < D_MID / 8; jb++) {
            u64 hb0, hb1, hb2, hb3;
            if (which == 0) {
                const ulonglong2* bp = reinterpret_cast<const ulonglong2*>(&sb[8 * jb]);
                ulonglong2 b01 = bp[0], b23 = bp[1];
                hb0 = b01.x; hb1 = b01.y; hb2 = b23.x; hb3 = b23.y;
            } else {
                hb0 = hb1 = hb2 = hb3 = 0ull;
            }
#pragma unroll
            for (int k = 0; k < IN_CH; k++) {
                u64 aa = pk2(xr[k], xr[k]);
                const ulonglong2* w = reinterpret_cast<const ulonglong2*>(Wbase + k * D_MID + 8 * jb);
                ulonglong2 w0 = w[0], w1 = w[1];
                FMA2(hb0, aa, w0.x, hb0);
                FMA2(hb1, aa, w0.y, hb1);
                FMA2(hb2, aa, w1.x, hb2);
                FMA2(hb3, aa, w1.y, hb3);
            }
            ulonglong2* dst = reinterpret_cast<ulonglong2*>(dstbase + 8 * jb);
            ulonglong2 s0; s0.x = hb0; s0.y = hb1;
            ulonglong2 s1; s1.x = hb2; s1.y = hb3;
            dst[0] = s0; dst[1] = s1;
        }
    }
}

// ---------------------------------------------------------------------------
// K2: per-edge MLP + scatter-max, j-blocked (h never fully live)  [round 6]
// ---------------------------------------------------------------------------
__global__ void __launch_bounds__(128, 6) k_edge(const int* __restrict__ idx32,
                                                 const float* __restrict__ edge_attr,
                                                 const float* __restrict__ W1,
                                                 const float* __restrict__ W2,
                                                 const float* __restrict__ b2,
                                                 float* __restrict__ out) {
    __shared__ __align__(16) float sWe[EDGE_CH * D_MID];   // 3584 B
    __shared__ __align__(16) float sW2[D_MID * OUT_CH];    // 7168 B
    __shared__ __align__(16) float sb2[OUT_CH];
    __shared__ float sea[128 * EA_PAD];                    // 8704 B

    const float* We = W1 + 2 * IN_CH * D_MID;
    for (int i = threadIdx.x; i < EDGE_CH * D_MID; i += blockDim.x) sWe[i] = We[i];
    for (int i = threadIdx.x; i < D_MID * OUT_CH; i += blockDim.x) sW2[i] = W2[i];
    for (int i = threadIdx.x; i < OUT_CH; i += blockDim.x) sb2[i] = b2[i];

    // stage this block's edge_attr tile (coalesced -> padded rows)
    int base = blockIdx.x * 128;
#pragma unroll
    for (int i = 0; i < 16; i++) {
        int local = threadIdx.x + 128 * i;
        int gidx  = base * EDGE_CH + local;
        float v = 0.0f;
        if (gidx < N_EDGES * EDGE_CH) v = edge_attr[gidx];
        sea[(local >> 4) * EA_PAD + (local & 15)] = v;
    }
    __syncthreads();

    int e = base + threadIdx.x;
    bool valid = e < N_EDGES;
    int ec = valid ? e : N_EDGES - 1;

    int rol, col;
    if (g_is64) {
        rol = idx32[2 * ec];
        col = idx32[2 * (N_EDGES + ec)];
    } else {
        rol = idx32[ec];
        col = idx32[N_EDGES + ec];
    }
    const ulonglong2* pr = reinterpret_cast<const ulonglong2*>(g_XR + (size_t)rol * D_MID);
    const ulonglong2* pc = reinterpret_cast<const ulonglong2*>(g_XC + (size_t)col * D_MID);
    const float* myea = &sea[threadIdx.x * EA_PAD];

    // persistent layer-2 accumulators
    u64 o[OUT_CH / 2];
    {
        const ulonglong2* bp = reinterpret_cast<const ulonglong2*>(sb2);
#pragma unroll
        for (int j = 0; j < OUT_CH / 4; j++) {
            ulonglong2 v = bp[j];
            o[2 * j] = v.x; o[2 * j + 1] = v.y;
        }
    }

#pragma unroll
    for (int jb = 0; jb < D_MID / 8; jb++) {
        // gathers for this 8-wide chunk (in flight behind the FMA block below)
        ulonglong2 r0 = pr[2 * jb], r1 = pr[2 * jb + 1];
        ulonglong2 c0 = pc[2 * jb], c1 = pc[2 * jb + 1];

        // layer 1a for this chunk: h[8jb..8jb+7] = edge_attr @ We[:, chunk]
        u64 hb0, hb1, hb2, hb3;
#pragma unroll
        for (int k = 0; k < EDGE_CH; k++) {
            float a = myea[k];
            u64 aa = pk2(a, a);
            const ulonglong2* w = reinterpret_cast<const ulonglong2*>(&sWe[k * D_MID + 8 * jb]);
            ulonglong2 w0 = w[0], w1 = w[1];
            if (k == 0) {
                MUL2(hb0, aa, w0.x);
                MUL2(hb1, aa, w0.y);
                MUL2(hb2, aa, w1.x);
                MUL2(hb3, aa, w1.y);
            } else {
                FMA2(hb0, aa, w0.x, hb0);
                FMA2(hb1, aa, w0.y, hb1);
                FMA2(hb2, aa, w1.x, hb2);
                FMA2(hb3, aa, w1.y, hb3);
            }
        }
        // add gathered XR + XC contributions
        ADD2(hb0, hb0, r0.x); ADD2(hb1, hb1, r0.y);
        ADD2(hb2, hb2, r1.x); ADD2(hb3, hb3, r1.y);
        ADD2(hb0, hb0, c0.x); ADD2(hb1, hb1, c0.y);
        ADD2(hb2, hb2, c1.x); ADD2(hb3, hb3, c1.y);

        // LeakyReLU + accumulate into o (h chunk dies here)
        u64 hbs[4] = {hb0, hb1, hb2, hb3};
#pragma unroll
        for (int p = 0; p < 4; p++) {
            float a, b; upk2(a, b, hbs[p]);
            a = fmaxf(a, 0.01f * a);
            b = fmaxf(b, 0.01f * b);
            u64 aa = pk2(a, a);
            u64 bb = pk2(b, b);
            const ulonglong2* wa = reinterpret_cast<const ulonglong2*>(&sW2[(8 * jb + 2 * p) * OUT_CH]);
            const ulonglong2* wb = reinterpret_cast<const ulonglong2*>(&sW2[(8 * jb + 2 * p + 1) * OUT_CH]);
#pragma unroll
            for (int j = 0; j < OUT_CH / 4; j++) {
                ulonglong2 w0 = wa[j];
                FMA2(o[2 * j],     aa, w0.x, o[2 * j]);
                FMA2(o[2 * j + 1], aa, w0.y, o[2 * j + 1]);
                ulonglong2 w1 = wb[j];
                FMA2(o[2 * j],     bb, w1.x, o[2 * j]);
                FMA2(o[2 * j + 1], bb, w1.y, o[2 * j + 1]);
            }
        }
    }

    // ---- LeakyReLU + filtered scatter-max ----
    if (valid) {
        float* orow = out + (size_t)col * OUT_CH;
        const float4* oro = reinterpret_cast<const float4*>(orow);
#pragma unroll
        for (int q = 0; q < OUT_CH / 4; q++) {
            float v0, v1, v2, v3;
            upk2(v0, v1, o[2 * q]);
            upk2(v2, v3, o[2 * q + 1]);
            v0 = fmaxf(v0, 0.01f * v0);
            v1 = fmaxf(v1, 0.01f * v1);
            v2 = fmaxf(v2, 0.01f * v2);
            v3 = fmaxf(v3, 0.01f * v3);
            float4 cur = oro[q];                 // monotone max: stale read is safe
            if (v0 > cur.x) atomicMaxF(orow + 4 * q + 0, v0);
            if (v1 > cur.y) atomicMaxF(orow + 4 * q + 1, v1);
            if (v2 > cur.z) atomicMaxF(orow + 4 * q + 2, v2);
            if (v3 > cur.w) atomicMaxF(orow + 4 * q + 3, v3);
        }
    }
}

// ---------------------------------------------------------------------------
// K3: finalize — -inf -> 0, elementwise max with x (float4)
// ---------------------------------------------------------------------------
__global__ void k_final(const float4* __restrict__ x, float4* __restrict__ out) {
    int i = blockIdx.x * blockDim.x + threadIdx.x;
    if (i >= N_NODES * OUT_CH / 4) return;
    float4 a = out[i];
    float4 b = x[i];
    if (__float_as_uint(a.x) == 0xFF800000u) a.x = 0.0f;
    if (__float_as_uint(a.y) == 0xFF800000u) a.y = 0.0f;
    if (__float_as_uint(a.z) == 0xFF800000u) a.z = 0.0f;
    if (__float_as_uint(a.w) == 0xFF800000u) a.w = 0.0f;
    a.x = fmaxf(a.x, b.x); a.y = fmaxf(a.y, b.y);
    a.z = fmaxf(a.z, b.z); a.w = fmaxf(a.w, b.w);
    out[i] = a;
}

// ---------------------------------------------------------------------------
extern "C" void kernel_launch(void* const* d_in, const int* in_sizes, int n_in,
                              void* d_out, int out_size) {
    const float* x         = (const float*)d_in[0];
    const int*   idx32     = (const int*)d_in[1];
    const float* edge_attr = (const float*)d_in[2];
    const float* W1        = (const float*)d_in[3];
    const float* b1        = (const float*)d_in[4];
    const float* W2        = (const float*)d_in[5];
    const float* b2        = (const float*)d_in[6];
    float* out = (float*)d_out;

    k_pre<<<(N_NODES * OUT_CH / 4 + 255) / 256, 256>>>((const unsigned int*)d_in[1], (uint4*)d_out);
    k_node<<<(N_NODES + 127) / 128, 128>>>(x, W1, b1);
    k_edge<<<(N_EDGES + 127) / 128, 128>>>(idx32, edge_attr, W1, W2, b2, out);
    k_final<<<(N_NODES * OUT_CH / 4 + 255) / 256, 256>>>((const float4*)x, (float4*)out);
}

// round 17
// speedup vs baseline: 1.6516x; 1.0837x over previous
#include <cuda_runtime.h>
#include <cstdint>

#define N_NODES 100000
#define N_EDGES 1000000
#define IN_CH   32
#define EDGE_CH 16
#define OUT_CH  32
#define D_MID   56
#define EA_PAD  17   // edge_attr smem row stride (conflict-free: 17 coprime 32)

typedef unsigned long long u64;

static __device__ int   g_is64;
static __device__ __align__(16) float g_XR[N_NODES * D_MID];  // x @ W1[0:32]  + b1
static __device__ __align__(16) float g_XC[N_NODES * D_MID];  // x @ W1[32:64]

// ---- packed f32x2 helpers ---------------------------------------------------
__device__ __forceinline__ u64 pk2(float a, float b) {
    u64 r; asm("mov.b64 %0, {%1,%2};" : "=l"(r) : "f"(a), "f"(b)); return r;
}
__device__ __forceinline__ void upk2(float& a, float& b, u64 v) {
    asm("mov.b64 {%0,%1}, %2;" : "=f"(a), "=f"(b) : "l"(v));
}
#define FMA2(d, a, b, c) asm("fma.rn.f32x2 %0, %1, %2, %3;" : "=l"(d) : "l"(a), "l"(b), "l"(c))
#define MUL2(d, a, b)    asm("mul.rn.f32x2 %0, %1, %2;"     : "=l"(d) : "l"(a), "l"(b))
#define ADD2(d, a, b)    asm("add.rn.f32x2 %0, %1, %2;"     : "=l"(d) : "l"(a), "l"(b))

__device__ __forceinline__ void atomicMaxF(float* addr, float val) {
    if (val >= 0.0f) atomicMax(reinterpret_cast<int*>(addr), __float_as_int(val));
    else             atomicMin(reinterpret_cast<unsigned int*>(addr), __float_as_uint(val));
}

// ---------------------------------------------------------------------------
// K0: one-shot init to -inf (uint4) + detect int64 (block 0)
// ---------------------------------------------------------------------------
__global__ void k_pre(const unsigned int* __restrict__ w, uint4* __restrict__ out) {
    if (blockIdx.x == 0) {
        __shared__ int bad;
        if (threadIdx.x == 0) bad = 0;
        __syncthreads();
        for (int i = threadIdx.x; i < 4096; i += blockDim.x)
            if (w[2 * i + 1] != 0u) bad = 1;   // benign race
        __syncthreads();
        if (threadIdx.x == 0) g_is64 = !bad;
    }
    int i = blockIdx.x * blockDim.x + threadIdx.x;
    if (i < N_NODES * OUT_CH / 4)
        out[i] = make_uint4(0xFF800000u, 0xFF800000u, 0xFF800000u, 0xFF800000u);
}

// ---------------------------------------------------------------------------
// K1: per-node precompute, j-blocked (low regs -> high occupancy)  [round 6]
// ---------------------------------------------------------------------------
__global__ void __launch_bounds__(128, 8) k_node(const float* __restrict__ x,
                                                 const float* __restrict__ W1,
                                                 const float* __restrict__ b1) {
    __shared__ __align__(16) float sW[2 * IN_CH * D_MID];  // 14336 B
    __shared__ __align__(16) float sb[D_MID];
    for (int i = threadIdx.x; i < 2 * IN_CH * D_MID; i += blockDim.x) sW[i] = W1[i];
    for (int i = threadIdx.x; i < D_MID; i += blockDim.x) sb[i] = b1[i];
    __syncthreads();

    int n = blockIdx.x * blockDim.x + threadIdx.x;
    if (n >= N_NODES) return;

    float xr[IN_CH];
    const float4* xp = reinterpret_cast<const float4*>(x + n * IN_CH);
#pragma unroll
    for (int c = 0; c < 8; c++) {
        float4 v = xp[c];
        xr[4 * c + 0] = v.x; xr[4 * c + 1] = v.y; xr[4 * c + 2] = v.z; xr[4 * c + 3] = v.w;
    }

#pragma unroll
    for (int which = 0; which < 2; which++) {
        float* dstbase = (which == 0 ? g_XR : g_XC) + (size_t)n * D_MID;
        const float* Wbase = sW + which * IN_CH * D_MID;
#pragma unroll
        for (int jb = 0; jb < D_MID / 8; jb++) {
            u64 hb0, hb1, hb2, hb3;
            if (which == 0) {
                const ulonglong2* bp = reinterpret_cast<const ulonglong2*>(&sb[8 * jb]);
                ulonglong2 b01 = bp[0], b23 = bp[1];
                hb0 = b01.x; hb1 = b01.y; hb2 = b23.x; hb3 = b23.y;
            } else {
                hb0 = hb1 = hb2 = hb3 = 0ull;
            }
#pragma unroll
            for (int k = 0; k < IN_CH; k++) {
                u64 aa = pk2(xr[k], xr[k]);
                const ulonglong2* w = reinterpret_cast<const ulonglong2*>(Wbase + k * D_MID + 8 * jb);
                ulonglong2 w0 = w[0], w1 = w[1];
                FMA2(hb0, aa, w0.x, hb0);
                FMA2(hb1, aa, w0.y, hb1);
                FMA2(hb2, aa, w1.x, hb2);
                FMA2(hb3, aa, w1.y, hb3);
            }
            ulonglong2* dst = reinterpret_cast<ulonglong2*>(dstbase + 8 * jb);
            ulonglong2 s0; s0.x = hb0; s0.y = hb1;
            ulonglong2 s1; s1.x = hb2; s1.y = hb3;
            dst[0] = s0; dst[1] = s1;
        }
    }
}

// ---------------------------------------------------------------------------
// K2: per-edge MLP + scatter-max, j-blocked, DOUBLE-BUFFERED chunk gathers.
// launch_bounds(128,5): 102-reg budget so ptxas can pipeline across chunks.
// ---------------------------------------------------------------------------
__global__ void __launch_bounds__(128, 5) k_edge(const int* __restrict__ idx32,
                                                 const float* __restrict__ edge_attr,
                                                 const float* __restrict__ W1,
                                                 const float* __restrict__ W2,
                                                 const float* __restrict__ b2,
                                                 float* __restrict__ out) {
    __shared__ __align__(16) float sWe[EDGE_CH * D_MID];   // 3584 B
    __shared__ __align__(16) float sW2[D_MID * OUT_CH];    // 7168 B
    __shared__ __align__(16) float sb2[OUT_CH];
    __shared__ float sea[128 * EA_PAD];                    // 8704 B

    const float* We = W1 + 2 * IN_CH * D_MID;
    for (int i = threadIdx.x; i < EDGE_CH * D_MID; i += blockDim.x) sWe[i] = We[i];
    for (int i = threadIdx.x; i < D_MID * OUT_CH; i += blockDim.x) sW2[i] = W2[i];
    for (int i = threadIdx.x; i < OUT_CH; i += blockDim.x) sb2[i] = b2[i];

    // stage this block's edge_attr tile (coalesced -> padded rows)
    int base = blockIdx.x * 128;
#pragma unroll
    for (int i = 0; i < 16; i++) {
        int local = threadIdx.x + 128 * i;
        int gidx  = base * EDGE_CH + local;
        float v = 0.0f;
        if (gidx < N_EDGES * EDGE_CH) v = edge_attr[gidx];
        sea[(local >> 4) * EA_PAD + (local & 15)] = v;
    }
    __syncthreads();

    int e = base + threadIdx.x;
    bool valid = e < N_EDGES;
    int ec = valid ? e : N_EDGES - 1;

    int rol, col;
    if (g_is64) {
        rol = idx32[2 * ec];
        col = idx32[2 * (N_EDGES + ec)];
    } else {
        rol = idx32[ec];
        col = idx32[N_EDGES + ec];
    }
    const ulonglong2* pr = reinterpret_cast<const ulonglong2*>(g_XR + (size_t)rol * D_MID);
    const ulonglong2* pc = reinterpret_cast<const ulonglong2*>(g_XC + (size_t)col * D_MID);
    const float* myea = &sea[threadIdx.x * EA_PAD];

    // persistent layer-2 accumulators
    u64 o[OUT_CH / 2];
    {
        const ulonglong2* bp = reinterpret_cast<const ulonglong2*>(sb2);
#pragma unroll
        for (int j = 0; j < OUT_CH / 4; j++) {
            ulonglong2 v = bp[j];
            o[2 * j] = v.x; o[2 * j + 1] = v.y;
        }
    }

    // prologue: chunk-0 gathers in flight
    ulonglong2 r0 = pr[0], r1 = pr[1];
    ulonglong2 c0 = pc[0], c1 = pc[1];

#pragma unroll
    for (int jb = 0; jb < D_MID / 8; jb++) {
        // prefetch NEXT chunk's gathers — a full FMA block of cover
        ulonglong2 nr0, nr1, nc0, nc1;
        if (jb < D_MID / 8 - 1) {
            nr0 = pr[2 * jb + 2]; nr1 = pr[2 * jb + 3];
            nc0 = pc[2 * jb + 2]; nc1 = pc[2 * jb + 3];
        }

        // layer 1a for this chunk: h[8jb..8jb+7] = edge_attr @ We[:, chunk]
        u64 hb0, hb1, hb2, hb3;
#pragma unroll
        for (int k = 0; k < EDGE_CH; k++) {
            float a = myea[k];
            u64 aa = pk2(a, a);
            const ulonglong2* w = reinterpret_cast<const ulonglong2*>(&sWe[k * D_MID + 8 * jb]);
            ulonglong2 w0 = w[0], w1 = w[1];
            if (k == 0) {
                MUL2(hb0, aa, w0.x);
                MUL2(hb1, aa, w0.y);
                MUL2(hb2, aa, w1.x);
                MUL2(hb3, aa, w1.y);
            } else {
                FMA2(hb0, aa, w0.x, hb0);
                FMA2(hb1, aa, w0.y, hb1);
                FMA2(hb2, aa, w1.x, hb2);
                FMA2(hb3, aa, w1.y, hb3);
            }
        }
        // add gathered XR + XC contributions (prefetched a full chunk ago)
        ADD2(hb0, hb0, r0.x); ADD2(hb1, hb1, r0.y);
        ADD2(hb2, hb2, r1.x); ADD2(hb3, hb3, r1.y);
        ADD2(hb0, hb0, c0.x); ADD2(hb1, hb1, c0.y);
        ADD2(hb2, hb2, c1.x); ADD2(hb3, hb3, c1.y);

        // rotate prefetch buffers
        r0 = nr0; r1 = nr1; c0 = nc0; c1 = nc1;

        // LeakyReLU + accumulate into o (h chunk dies here)
        u64 hbs[4] = {hb0, hb1, hb2, hb3};
#pragma unroll
        for (int p = 0; p < 4; p++) {
            float a, b; upk2(a, b, hbs[p]);
            a = fmaxf(a, 0.01f * a);
            b = fmaxf(b, 0.01f * b);
            u64 aa = pk2(a, a);
            u64 bb = pk2(b, b);
            const ulonglong2* wa = reinterpret_cast<const ulonglong2*>(&sW2[(8 * jb + 2 * p) * OUT_CH]);
            const ulonglong2* wb = reinterpret_cast<const ulonglong2*>(&sW2[(8 * jb + 2 * p + 1) * OUT_CH]);
#pragma unroll
            for (int j = 0; j < OUT_CH / 4; j++) {
                ulonglong2 w0 = wa[j];
                FMA2(o[2 * j],     aa, w0.x, o[2 * j]);
                FMA2(o[2 * j + 1], aa, w0.y, o[2 * j + 1]);
                ulonglong2 w1 = wb[j];
                FMA2(o[2 * j],     bb, w1.x, o[2 * j]);
                FMA2(o[2 * j + 1], bb, w1.y, o[2 * j + 1]);
            }
        }
    }

    // ---- LeakyReLU + filtered scatter-max ----
    if (valid) {
        float* orow = out + (size_t)col * OUT_CH;
        const float4* oro = reinterpret_cast<const float4*>(orow);
#pragma unroll
        for (int q = 0; q < OUT_CH / 4; q++) {
            float v0, v1, v2, v3;
            upk2(v0, v1, o[2 * q]);
            upk2(v2, v3, o[2 * q + 1]);
            v0 = fmaxf(v0, 0.01f * v0);
            v1 = fmaxf(v1, 0.01f * v1);
            v2 = fmaxf(v2, 0.01f * v2);
            v3 = fmaxf(v3, 0.01f * v3);
            float4 cur = oro[q];                 // monotone max: stale read is safe
            if (v0 > cur.x) atomicMaxF(orow + 4 * q + 0, v0);
            if (v1 > cur.y) atomicMaxF(orow + 4 * q + 1, v1);
            if (v2 > cur.z) atomicMaxF(orow + 4 * q + 2, v2);
            if (v3 > cur.w) atomicMaxF(orow + 4 * q + 3, v3);
        }
    }
}

// ---------------------------------------------------------------------------
// K3: finalize — -inf -> 0, elementwise max with x (float4)
// ---------------------------------------------------------------------------
__global__ void k_final(const float4* __restrict__ x, float4* __restrict__ out) {
    int i = blockIdx.x * blockDim.x + threadIdx.x;
    if (i >= N_NODES * OUT_CH / 4) return;
    float4 a = out[i];
    float4 b = x[i];
    if (__float_as_uint(a.x) == 0xFF800000u) a.x = 0.0f;
    if (__float_as_uint(a.y) == 0xFF800000u) a.y = 0.0f;
    if (__float_as_uint(a.z) == 0xFF800000u) a.z = 0.0f;
    if (__float_as_uint(a.w) == 0xFF800000u) a.w = 0.0f;
    a.x = fmaxf(a.x, b.x); a.y = fmaxf(a.y, b.y);
    a.z = fmaxf(a.z, b.z); a.w = fmaxf(a.w, b.w);
    out[i] = a;
}

// ---------------------------------------------------------------------------
extern "C" void kernel_launch(void* const* d_in, const int* in_sizes, int n_in,
                              void* d_out, int out_size) {
    const float* x         = (const float*)d_in[0];
    const int*   idx32     = (const int*)d_in[1];
    const float* edge_attr = (const float*)d_in[2];
    const float* W1        = (const float*)d_in[3];
    const float* b1        = (const float*)d_in[4];
    const float* W2        = (const float*)d_in[5];
    const float* b2        = (const float*)d_in[6];
    float* out = (float*)d_out;

    k_pre<<<(N_NODES * OUT_CH / 4 + 255) / 256, 256>>>((const unsigned int*)d_in[1], (uint4*)d_out);
    k_node<<<(N_NODES + 127) / 128, 128>>>(x, W1, b1);
    k_edge<<<(N_EDGES + 127) / 128, 128>>>(idx32, edge_attr, W1, W2, b2, out);
    k_final<<<(N_NODES * OUT_CH / 4 + 255) / 256, 256>>>((const float4*)x, (float4*)out);
}